// round 8
// baseline (speedup 1.0000x reference)
#include <cuda_runtime.h>
#include <cuda_bf16.h>
#include <cstdint>

// Problem shapes (fixed by the dataset)
#define BB 16
#define TT 128
#define HH 512
#define VV 32000
#define SS 400
#define ROWS (BB * TT)          // 2048
#define NTHREADS 512
#define V4 (VV / 4)             // 8000 float4 per row = 15*512 + 320

// p_gen scratch, written by gate kernel, read by stream kernel (graph-ordered)
__device__ float g_pgen[ROWS];

// ---------------------------------------------------------------------------
// K1: warp-per-row gate.  grid = ROWS/8 CTAs of 256 threads (8 warps/CTA).
// Each lane handles 16 hidden elems at stride 32 (fully coalesced).
// ---------------------------------------------------------------------------
__global__ __launch_bounds__(256)
void gate_kernel(const float* __restrict__ ctx,
                 const float* __restrict__ hid,
                 const float* __restrict__ trg,
                 const float* __restrict__ w_h,
                 const float* __restrict__ w_s,
                 const float* __restrict__ w_x,
                 const float* __restrict__ w_b)
{
    const int warp = (blockIdx.x * 256 + threadIdx.x) >> 5;   // row id
    const int lane = threadIdx.x & 31;
    if (warp >= ROWS) return;

    const size_t base = (size_t)warp * HH + lane;
    float part = 0.0f;
    #pragma unroll
    for (int j = 0; j < 16; j++) {
        const int o = lane + 32 * j;
        part += ctx[base + 32 * j] * w_h[o]
              + hid[base + 32 * j] * w_s[o]
              + trg[base + 32 * j] * w_x[o];
    }
    #pragma unroll
    for (int o = 16; o > 0; o >>= 1)
        part += __shfl_xor_sync(0xFFFFFFFFu, part, o);

    if (lane == 0) {
        const float z = part + w_b[0];
        g_pgen[warp] = 1.0f / (1.0f + __expf(-z));
    }
}

// ---------------------------------------------------------------------------
// K2: pure stream + scatter.  One CTA per row, no reduce, no smem, a single
// barrier ordering this row's plain stores before this row's atomics.
// ---------------------------------------------------------------------------
__global__ __launch_bounds__(NTHREADS, 2)
void scale_scatter_kernel(const float* __restrict__ vocab,   // [ROWS, V]
                          const float* __restrict__ attn,    // [ROWS, S]
                          const int*   __restrict__ srcids,  // [ROWS, S]
                          float* __restrict__ out)           // [ROWS, V]
{
    const int row = blockIdx.x;
    const int tid = threadIdx.x;

    const float pg  = g_pgen[row];          // scalar, L2-hot after K1
    const float omp = 1.0f - pg;

    const float4* __restrict__ vin =
        reinterpret_cast<const float4*>(vocab + (size_t)row * VV);
    float4* __restrict__ vout =
        reinterpret_cast<float4*>(out + (size_t)row * VV);

    // ---- prefetch scatter operands into registers (evict-first) ----
    float av = 0.0f;
    int   idv = 0;
    if (tid < SS) {
        av  = __ldcs(attn   + (size_t)row * SS + tid);
        idv = __ldcs(srcids + (size_t)row * SS + tid);
    }

    // ---- uninterrupted stream: batches of 8 / 7 / partial ----
    float4 buf[8];

    #pragma unroll
    for (int u = 0; u < 8; u++)
        buf[u] = __ldcs(vin + tid + u * NTHREADS);
    #pragma unroll
    for (int u = 0; u < 8; u++) {
        float4 v = buf[u];
        v.x *= pg; v.y *= pg; v.z *= pg; v.w *= pg;
        vout[tid + u * NTHREADS] = v;
    }

    #pragma unroll
    for (int u = 0; u < 7; u++)
        buf[u] = __ldcs(vin + tid + (8 + u) * NTHREADS);
    #pragma unroll
    for (int u = 0; u < 7; u++) {
        float4 v = buf[u];
        v.x *= pg; v.y *= pg; v.z *= pg; v.w *= pg;
        vout[tid + (8 + u) * NTHREADS] = v;
    }

    // partial iter 15: indices 7680 + tid for tid < 320
    if (tid < (V4 - 15 * NTHREADS)) {
        float4 v = __ldcs(vin + tid + 15 * NTHREADS);
        v.x *= pg; v.y *= pg; v.z *= pg; v.w *= pg;
        vout[tid + 15 * NTHREADS] = v;
    }

    // Order this row's plain stores before this row's atomics (CTA scope;
    // both meet in L2).
    __syncthreads();

    // ---- scatter-add: operands already in registers ----
    if (tid < SS) {
        atomicAdd(out + (size_t)row * VV + idv, omp * av);
    }
}

extern "C" void kernel_launch(void* const* d_in, const int* in_sizes, int n_in,
                              void* d_out, int out_size)
{
    // metadata order: context_vecs, hidden, trg_embs, vocab_dists, attn_dists,
    //                 src_ids, pad_id(unused), w_h, w_s, w_x_w, w_x_b
    const float* ctx    = (const float*)d_in[0];
    const float* hid    = (const float*)d_in[1];
    const float* trg    = (const float*)d_in[2];
    const float* vocab  = (const float*)d_in[3];
    const float* attn   = (const float*)d_in[4];
    const int*   srcids = (const int*)  d_in[5];
    const float* w_h    = (const float*)d_in[7];
    const float* w_s    = (const float*)d_in[8];
    const float* w_x    = (const float*)d_in[9];
    const float* w_b    = (const float*)d_in[10];
    float* out = (float*)d_out;

    gate_kernel<<<ROWS / 8, 256>>>(ctx, hid, trg, w_h, w_s, w_x, w_b);
    scale_scatter_kernel<<<ROWS, NTHREADS>>>(vocab, attn, srcids, out);
}